// round 1
// baseline (speedup 1.0000x reference)
#include <cuda_runtime.h>

// Geometry (fixed by the problem)
#define B_    4
#define CIN_  8
#define H_    64
#define W_    64
#define COUT_ 32
#define KH_   3
#define KW_   3
#define K_    72      // CIN*KH*KW
#define L_    4096    // HO*WO
#define HO_   64
#define WO_   64
#define POT_ELEMS (B_*COUT_*L_)          // 524288
#define ROWS_PER_BLK 16                   // 1024 l-values per block / 64 wo

__global__ __launch_bounds__(256, 4)
void conv2d_expdelay_kernel(
    const float* __restrict__ x,          // [B, CIN, H, W]
    const float* __restrict__ weight,     // [COUT, K]
    const float* __restrict__ trace,      // [B, COUT, K, L]
    const float* __restrict__ delay,      // [B, COUT, K, L]
    const float* __restrict__ dinit,      // [B, COUT, K, L]
    const float* __restrict__ p_alpha,
    const float* __restrict__ p_tau,
    const float* __restrict__ p_dt,
    float* __restrict__ out)              // [pot | trace_new]
{
    // smem x tile: CIN x (ROWS+2) x (WO+2), padded cols to 68 to dodge conflicts
    __shared__ float xs[CIN_][ROWS_PER_BLK + 2][68];
    __shared__ float ws[K_];

    const int bo  = blockIdx.y;           // b*COUT + o
    const int o   = bo & (COUT_ - 1);
    const int b   = bo >> 5;
    const int row0 = blockIdx.x * ROWS_PER_BLK;   // ho base of this tile
    const int tid  = threadIdx.x;

    if (tid < K_) ws[tid] = weight[o * K_ + tid];

    // Load padded x tile: 8 * 18 * 66 = 9504 elements
    for (int i = tid; i < CIN_ * (ROWS_PER_BLK + 2) * 66; i += 256) {
        int c   = i / ((ROWS_PER_BLK + 2) * 66);
        int rem = i % ((ROWS_PER_BLK + 2) * 66);
        int r   = rem / 66;
        int col = rem % 66;
        int gh = row0 + r - 1;
        int gw = col - 1;
        float v = 0.0f;
        if (gh >= 0 && gh < H_ && gw >= 0 && gw < W_)
            v = x[((b * CIN_ + c) * H_ + gh) * W_ + gw];
        xs[c][r][col] = v;
    }
    __syncthreads();

    const float alpha = *p_alpha;
    const float coeff = (*p_dt) / (*p_tau);

    const int l0   = blockIdx.x * (ROWS_PER_BLK * WO_) + tid * 4;  // global l
    const int lrow = (tid * 4) >> 6;     // row within tile (0..15), 4 l's share a row
    const int wo   = (tid * 4) & 63;

    const size_t base_bo = (size_t)bo * K_ * L_;
    float* __restrict__ trout = out + POT_ELEMS;

    float4 pot = make_float4(0.f, 0.f, 0.f, 0.f);

    int k = 0;
    #pragma unroll
    for (int c = 0; c < CIN_; ++c) {
        #pragma unroll
        for (int kh = 0; kh < KH_; ++kh) {
            const float* xrow = &xs[c][lrow + kh][wo];
            #pragma unroll
            for (int kw = 0; kw < KW_; ++kw, ++k) {
                const size_t idx = base_bo + (size_t)k * L_ + l0;
                const float4 t4 = *reinterpret_cast<const float4*>(trace + idx);
                const float4 d4 = *reinterpret_cast<const float4*>(delay + idx);
                const float4 i4 = *reinterpret_cast<const float4*>(dinit + idx);

                const float xu0 = xrow[kw + 0];
                const float xu1 = xrow[kw + 1];
                const float xu2 = xrow[kw + 2];
                const float xu3 = xrow[kw + 3];

                // trace_new = trace + coeff*(alpha*xu - trace)
                float4 tn;
                tn.x = fmaf(coeff, fmaf(alpha, xu0, -t4.x), t4.x);
                tn.y = fmaf(coeff, fmaf(alpha, xu1, -t4.y), t4.y);
                tn.z = fmaf(coeff, fmaf(alpha, xu2, -t4.z), t4.z);
                tn.w = fmaf(coeff, fmaf(alpha, xu3, -t4.w), t4.w);
                *reinterpret_cast<float4*>(trout + idx) = tn;

                // spike = (delay + xu*delay_init == 1.0f); pot += spike * w
                const float w = ws[k];
                pot.x += (fmaf(xu0, i4.x, d4.x) == 1.0f) ? w : 0.0f;
                pot.y += (fmaf(xu1, i4.y, d4.y) == 1.0f) ? w : 0.0f;
                pot.z += (fmaf(xu2, i4.z, d4.z) == 1.0f) ? w : 0.0f;
                pot.w += (fmaf(xu3, i4.w, d4.w) == 1.0f) ? w : 0.0f;
            }
        }
    }

    *reinterpret_cast<float4*>(out + (size_t)bo * L_ + l0) = pot;
}

extern "C" void kernel_launch(void* const* d_in, const int* in_sizes, int n_in,
                              void* d_out, int out_size) {
    const float* x      = (const float*)d_in[0];
    const float* weight = (const float*)d_in[1];
    const float* trace  = (const float*)d_in[2];
    const float* delay  = (const float*)d_in[3];
    const float* dinit  = (const float*)d_in[4];
    const float* alpha  = (const float*)d_in[5];
    const float* tau    = (const float*)d_in[6];
    const float* dt     = (const float*)d_in[7];
    float* out = (float*)d_out;

    dim3 grid(L_ / (ROWS_PER_BLK * WO_), B_ * COUT_);   // (4, 128)
    conv2d_expdelay_kernel<<<grid, 256>>>(x, weight, trace, delay, dinit,
                                          alpha, tau, dt, out);
}